// round 3
// baseline (speedup 1.0000x reference)
#include <cuda_runtime.h>
#include <math.h>

// Problem constants (B=1)
#define Lc     2048
#define Hc     16
#define Dc     64
#define Mc     24
#define Wc     128
#define CHUNK  128
#define NC     16
#define SCALEc 0.125f
#define EPSc   1e-4f
#define DN     0.35355339059327373f   // sqrt(0.125)
#define LN24   3.1780538303479458f    // log(24)

typedef unsigned long long U64;

__device__ __forceinline__ U64 fma2(U64 a, U64 b, U64 c) {
    U64 d; asm("fma.rn.f32x2 %0, %1, %2, %3;" : "=l"(d) : "l"(a), "l"(b), "l"(c)); return d;
}
__device__ __forceinline__ U64 mul2(U64 a, U64 b) {
    U64 d; asm("mul.rn.f32x2 %0, %1, %2;" : "=l"(d) : "l"(a), "l"(b)); return d;
}
__device__ __forceinline__ U64 add2(U64 a, U64 b) {
    U64 d; asm("add.rn.f32x2 %0, %1, %2;" : "=l"(d) : "l"(a), "l"(b)); return d;
}
__device__ __forceinline__ U64 pack2(float x, float y) {
    U64 d; asm("mov.b64 %0, {%1,%2};" : "=l"(d)
               : "r"(__float_as_uint(x)), "r"(__float_as_uint(y))); return d;
}
__device__ __forceinline__ float hadd2(U64 a) {
    unsigned lo, hi; asm("mov.b64 {%0,%1}, %2;" : "=r"(lo), "=r"(hi) : "l"(a));
    return __uint_as_float(lo) + __uint_as_float(hi);
}
__device__ __forceinline__ void unpack2(float& x, float& y, U64 a) {
    unsigned lo, hi; asm("mov.b64 {%0,%1}, %2;" : "=r"(lo), "=r"(hi) : "l"(a));
    x = __uint_as_float(lo); y = __uint_as_float(hi);
}

// ---------------- scratch ----------------
__device__ float g_xdash[Hc * NC * Mc * CHUNK];
__device__ float g_xn[Hc * NC * CHUNK];
__device__ float g_kprime[Hc * Lc * Mc];
__device__ float g_chunkmax[Hc * NC];
__device__ float g_kstab[Hc];
__device__ float g_ksum [Hc * NC * Mc];
__device__ float g_kvsum[Hc * NC * Mc * Dc];
__device__ float g_kbase [Hc * NC * Mc];
__device__ float g_kvbase[Hc * NC * Mc * Dc];

// ---------------- kernel 1: key features + chunk max ------
__global__ void __launch_bounds__(128) k1_feat(const float* __restrict__ qkv,
                                               const float* __restrict__ proj)
{
    __shared__ float proj_s[Mc * Dc];
    __shared__ float red[128];
    const int c = blockIdx.x, h = blockIdx.y, t = threadIdx.x;
    const int hc = h * NC + c;

    for (int f = t; f < Mc * Dc / 4; f += 128)
        ((float4*)proj_s)[f] = ((const float4*)proj)[f];
    __syncthreads();

    const int l = c * CHUNK + t;
    float k[Dc];
    const float4* kr = (const float4*)(qkv + ((size_t)(l * 3 + 1) * Hc + h) * Dc);
#pragma unroll
    for (int dv = 0; dv < 16; dv++) {
        float4 x = kr[dv];
        k[4*dv] = x.x; k[4*dv+1] = x.y; k[4*dv+2] = x.z; k[4*dv+3] = x.w;
    }
    float xn = 0.f;
#pragma unroll
    for (int d = 0; d < Dc; d++) xn = fmaf(k[d], k[d], xn);
    g_xn[hc * CHUNK + t] = xn * 0.0625f;

    float mx = -3.4e38f;
#pragma unroll
    for (int m = 0; m < Mc; m++) {
        const float* pr = proj_s + m * Dc;
        float d0 = 0.f, d1 = 0.f, d2 = 0.f, d3 = 0.f;
#pragma unroll
        for (int d = 0; d < Dc; d += 4) {
            d0 = fmaf(pr[d  ], k[d  ], d0);
            d1 = fmaf(pr[d+1], k[d+1], d1);
            d2 = fmaf(pr[d+2], k[d+2], d2);
            d3 = fmaf(pr[d+3], k[d+3], d3);
        }
        float xd = ((d0 + d1) + (d2 + d3)) * DN;
        g_xdash[(hc * Mc + m) * CHUNK + t] = xd;
        mx = fmaxf(mx, xd);
    }
    red[t] = mx;
    __syncthreads();
    for (int s = 64; s > 0; s >>= 1) {
        if (t < s) red[t] = fmaxf(red[t], red[t + s]);
        __syncthreads();
    }
    if (t == 0) g_chunkmax[hc] = red[0];
}

// ---------------- kernel 2: k' + per-chunk sums ------------
__global__ void __launch_bounds__(128) k2_kprime(const float* __restrict__ qkv)
{
    __shared__ float vbuf[CHUNK * Dc];
    __shared__ float kp_s[CHUNK * 25];
    const int c = blockIdx.x, h = blockIdx.y, t = threadIdx.x;
    const int hc = h * NC + c;

    float kstab = -3.4e38f;
#pragma unroll
    for (int cc = 0; cc < NC; cc++) kstab = fmaxf(kstab, g_chunkmax[h * NC + cc]);
    if (c == 0 && t == 0) g_kstab[h] = kstab;

    const int tilebase = c * CHUNK;
    for (int f = t; f < CHUNK * 16; f += 128) {
        int r = f >> 4, dv = f & 15;
        ((float4*)vbuf)[f] =
            ((const float4*)(qkv + ((size_t)((tilebase + r) * 3 + 2) * Hc + h) * Dc))[dv];
    }

    const float xn = g_xn[hc * CHUNK + t];
    const int l = tilebase + t;
    float* kpo = g_kprime + ((size_t)h * Lc + l) * Mc;
#pragma unroll
    for (int m = 0; m < Mc; m++) {
        float xd = g_xdash[(hc * Mc + m) * CHUNK + t];
        float val = __expf(xd - xn - kstab) + EPSc;
        kp_s[t * 25 + m] = val;
        kpo[m] = val;
    }
    __syncthreads();

    float4* kvo4 = (float4*)(g_kvsum + (size_t)hc * Mc * Dc);
    const float4* vb4 = (const float4*)vbuf;
#pragma unroll
    for (int grp = 0; grp < 3; grp++) {
        int o = t + 128 * grp;
        int m = o >> 4, d4 = o & 15;
        float4 a = make_float4(0.f, 0.f, 0.f, 0.f);
        for (int row = 0; row < CHUNK; row++) {
            float kp = kp_s[row * 25 + m];
            float4 v = vb4[row * 16 + d4];
            a.x = fmaf(kp, v.x, a.x);
            a.y = fmaf(kp, v.y, a.y);
            a.z = fmaf(kp, v.z, a.z);
            a.w = fmaf(kp, v.w, a.w);
        }
        kvo4[o] = a;
    }
    if (t < Mc) {
        float a = 0.f;
        for (int row = 0; row < CHUNK; row++) a += kp_s[row * 25 + t];
        g_ksum[hc * Mc + t] = a;
    }
}

// ---------------- kernel 3: exclusive scan -----------------
__global__ void __launch_bounds__(256) k3_scan()
{
    const int h = blockIdx.x, t = threadIdx.x;
    for (int e = t; e < Mc * Dc; e += 256) {
        float run = 0.f;
#pragma unroll
        for (int c = 0; c < NC; c++) {
            size_t idx = ((size_t)(h * NC + c)) * Mc * Dc + e;
            g_kvbase[idx] = run;
            run += g_kvsum[idx];
        }
    }
    if (t < Mc) {
        float run = 0.f;
#pragma unroll
        for (int c = 0; c < NC; c++) {
            int idx = (h * NC + c) * Mc + t;
            g_kbase[idx] = run;
            run += g_ksum[idx];
        }
    }
}

// ---------------- kernel 4: fused single-pass, f32x2, pair-split ----------
// smem layout (floats), 16B-aligned rows, bank-staggered halves:
//   K0 @ 0      : 256*32
//   K1 @ 8196   : 256*32   (stagger +4 floats -> odd lanes hit disjoint banks)
//   KP0 @ 16388 : 256*12
//   KP1 @ 19464 : 256*12
#define OFF_K0   0
#define OFF_K1   8196
#define OFF_KP0  16388
#define OFF_KP1  19464
#define SM5_FLOATS (19464 + 3072 + 8)

__global__ void __launch_bounds__(256, 1) k4_main(const float* __restrict__ qkv,
                                                  const float* __restrict__ proj,
                                                  float* __restrict__ out)
{
    extern __shared__ float sm[];
    const int c = blockIdx.x, h = blockIdx.y, t = threadIdx.x;
    const int half = t & 1;                  // which 32 of 64 dims
    const int i    = c * CHUNK + (t >> 1);   // query index
    const int tilebase = (c > 0) ? (c - 1) * CHUNK : 0;
    const int nkeys    = (c > 0) ? 256 : 128;
    const int cstart   = c * CHUNK;

    // ---- cooperative tile fill (K and kp, split halves with stagger) ----
    for (int f = t; f < nkeys * 16; f += 256) {
        int r = f >> 4, dv = f & 15;
        float4 x = ((const float4*)(qkv + ((size_t)((tilebase + r) * 3 + 1) * Hc + h) * Dc))[dv];
        int base = (dv < 8) ? (OFF_K0 + r * 32 + dv * 4) : (OFF_K1 + r * 32 + (dv - 8) * 4);
        *((float4*)(sm + base)) = x;
    }
    {
        const float4* kpsrc = (const float4*)(g_kprime + ((size_t)h * Lc + tilebase) * Mc);
        for (int f = t; f < nkeys * 6; f += 256) {
            int r = f / 6, e = f % 6;
            float4 x = kpsrc[f];
            int base = (e < 3) ? (OFF_KP0 + r * 12 + e * 4) : (OFF_KP1 + r * 12 + (e - 3) * 4);
            *((float4*)(sm + base)) = x;
        }
    }

    // ---- prologue: query features (independent of smem; overlaps fill) ----
    U64 q2[16];
    {
        const ulonglong2* qr = (const ulonglong2*)(qkv + ((size_t)(i * 3 + 0) * Hc + h) * Dc + half * 32);
#pragma unroll
        for (int u = 0; u < 8; u++) { ulonglong2 x = qr[u]; q2[2*u] = x.x; q2[2*u+1] = x.y; }
    }
    float xn;
    {
        U64 a0 = mul2(q2[0], q2[0]), a1 = mul2(q2[1], q2[1]);
#pragma unroll
        for (int u = 2; u < 16; u += 2) {
            a0 = fma2(q2[u], q2[u], a0);
            a1 = fma2(q2[u+1], q2[u+1], a1);
        }
        float p = hadd2(add2(a0, a1));
        p += __shfl_xor_sync(0xffffffffu, p, 1);
        xn = p * 0.0625f;
    }
    float xd[Mc];
    float qstab = -3.4e38f;
#pragma unroll
    for (int m = 0; m < Mc; m++) {
        const ulonglong2* pr = (const ulonglong2*)(proj + m * Dc + half * 32);
        ulonglong2 p0 = pr[0], p1 = pr[1], p2_ = pr[2], p3 = pr[3];
        U64 a0 = mul2(q2[0], p0.x), a1 = mul2(q2[1], p0.y);
        a0 = fma2(q2[2], p1.x, a0);  a1 = fma2(q2[3], p1.y, a1);
        a0 = fma2(q2[4], p2_.x, a0); a1 = fma2(q2[5], p2_.y, a1);
        a0 = fma2(q2[6], p3.x, a0);  a1 = fma2(q2[7], p3.y, a1);
        const ulonglong2* pr2 = pr + 4;
        ulonglong2 p4 = pr2[0], p5 = pr2[1], p6 = pr2[2], p7 = pr2[3];
        a0 = fma2(q2[8],  p4.x, a0); a1 = fma2(q2[9],  p4.y, a1);
        a0 = fma2(q2[10], p5.x, a0); a1 = fma2(q2[11], p5.y, a1);
        a0 = fma2(q2[12], p6.x, a0); a1 = fma2(q2[13], p6.y, a1);
        a0 = fma2(q2[14], p7.x, a0); a1 = fma2(q2[15], p7.y, a1);
        float p = hadd2(add2(a0, a1));
        p += __shfl_xor_sync(0xffffffffu, p, 1);
        xd[m] = p * DN;
        qstab = fmaxf(qstab, xd[m]);
    }
    U64 qp2[12];
#pragma unroll
    for (int e = 0; e < 12; e++) {
        float a = __expf(xd[2*e]   - qstab) + EPSc;
        float b = __expf(xd[2*e+1] - qstab) + EPSc;
        qp2[e] = pack2(a, b);
    }

    const float kstab = g_kstab[h];
    const float gs = qstab - xn + kstab - LN24;
    float kbdot = 0.f;
    {
        const float* kb = g_kbase + (h * NC + c) * Mc;
#pragma unroll
        for (int e = 0; e < 12; e++) {
            float a, b; unpack2(a, b, qp2[e]);
            kbdot = fmaf(a, __ldg(kb + 2*e), kbdot);
            kbdot = fmaf(b, __ldg(kb + 2*e + 1), kbdot);
        }
    }
    __syncthreads();

    // ---- fused main loop ----
    const float* kbase  = sm + (half ? OFF_K1 : OFF_K0);
    const float* kpbase = sm + (half ? OFF_KP1 : OFF_KP0);
    const int qw = c * CHUNK + (t >> 5) * 16;     // warp's first query
    int jlo = qw - Wc; if (jlo < tilebase) jlo = tilebase;
    const int jhi = qw + 15;

    U64 P2[16], G2[16];
#pragma unroll
    for (int u = 0; u < 16; u++) { P2[u] = 0ULL; G2[u] = 0ULL; }
    float Z = 0.f, Asc = 0.f;

    for (int jg = jlo; jg <= jhi; jg++) {
        const int j = jg - tilebase;
        const ulonglong2* kr = (const ulonglong2*)(kbase + j * 32);
        const ulonglong2* kpr = (const ulonglong2*)(kpbase + j * 12);
        const ulonglong2* vr = (const ulonglong2*)(qkv + ((size_t)(jg * 3 + 2) * Hc + h) * Dc + half * 32);

        // s partial (own 32 dims)
        ulonglong2 k0 = kr[0], k1 = kr[1], k2_ = kr[2], k3 = kr[3];
        U64 s0 = mul2(q2[0], k0.x), s1 = mul2(q2[1], k0.y);
        s0 = fma2(q2[2], k1.x, s0);  s1 = fma2(q2[3], k1.y, s1);
        s0 = fma2(q2[4], k2_.x, s0); s1 = fma2(q2[5], k2_.y, s1);
        s0 = fma2(q2[6], k3.x, s0);  s1 = fma2(q2[7], k3.y, s1);
        ulonglong2 k4 = kr[4], k5 = kr[5], k6 = kr[6], k7 = kr[7];
        s0 = fma2(q2[8],  k4.x, s0); s1 = fma2(q2[9],  k4.y, s1);
        s0 = fma2(q2[10], k5.x, s0); s1 = fma2(q2[11], k5.y, s1);
        s0 = fma2(q2[12], k6.x, s0); s1 = fma2(q2[13], k6.y, s1);
        s0 = fma2(q2[14], k7.x, s0); s1 = fma2(q2[15], k7.y, s1);
        float sp = hadd2(add2(s0, s1));
        sp += __shfl_xor_sync(0xffffffffu, sp, 1);
        const float s = sp * SCALEc;

        // g partial (own 12 features)
        ulonglong2 c0 = kpr[0], c1 = kpr[1], c2 = kpr[2];
        const int qb = half * 6;
        U64 g0 = mul2(qp2[qb + 0], c0.x);
        U64 g1 = mul2(qp2[qb + 1], c0.y);
        g0 = fma2(qp2[qb + 2], c1.x, g0);
        g1 = fma2(qp2[qb + 3], c1.y, g1);
        g0 = fma2(qp2[qb + 4], c2.x, g0);
        g1 = fma2(qp2[qb + 5], c2.y, g1);
        float gp = hadd2(add2(g0, g1));
        gp += __shfl_xor_sync(0xffffffffu, gp, 1);

        const bool act = (jg <= i) && (jg >= i - Wc);
        const float w = (jg >= cstart) ? 0.875f : -0.125f;
        const float cp = act ? __expf(s) : 0.f;
        const float cg = act ? (w * gp) : 0.f;
        Z += cp; Asc += cg;
        const U64 cp2 = pack2(cp, cp), cg2 = pack2(cg, cg);

#pragma unroll
        for (int u = 0; u < 8; u++) {
            ulonglong2 vv = vr[u];
            P2[2*u]   = fma2(cp2, vv.x, P2[2*u]);
            P2[2*u+1] = fma2(cp2, vv.y, P2[2*u+1]);
            G2[2*u]   = fma2(cg2, vv.x, G2[2*u]);
            G2[2*u+1] = fma2(cg2, vv.y, G2[2*u+1]);
        }
    }

    // ---- normalization scalars ----
    const float lse = __logf(Z);
    const float gln = __logf(fmaxf(kbdot + Asc, 1e-24f)) + gs;
    float a_ = fmaxf(lse, gln), b_ = fminf(lse, gln);
    const float lnorm = a_ + log1pf(__expf(b_ - a_));
    const float gps = __expf(gs - lnorm);
    const float invZ = 1.f / Z;

    // ---- epilogue: G += q' . KVbase (own half), then o = P*invZ + gps*G ----
    const float* kvb = g_kvbase + ((size_t)(h * NC + c)) * Mc * Dc + half * 32;
#pragma unroll
    for (int e = 0; e < 12; e++) {
        float qa, qb_; unpack2(qa, qb_, qp2[e]);
        U64 qa2 = pack2(qa, qa), qb2 = pack2(qb_, qb_);
        const ulonglong2* r0 = (const ulonglong2*)(kvb + (2*e) * Dc);
        const ulonglong2* r1 = (const ulonglong2*)(kvb + (2*e+1) * Dc);
#pragma unroll
        for (int u = 0; u < 8; u++) {
            ulonglong2 x0 = r0[u], x1 = r1[u];
            G2[2*u]   = fma2(qa2, x0.x, G2[2*u]);
            G2[2*u+1] = fma2(qa2, x0.y, G2[2*u+1]);
            G2[2*u]   = fma2(qb2, x1.x, G2[2*u]);
            G2[2*u+1] = fma2(qb2, x1.y, G2[2*u+1]);
        }
    }
    const U64 iz2 = pack2(invZ, invZ), gp2 = pack2(gps, gps);
    ulonglong2* orow = (ulonglong2*)(out + ((size_t)i * Hc + h) * Dc + half * 32);
#pragma unroll
    for (int u = 0; u < 8; u++) {
        U64 oa = fma2(gp2, G2[2*u],   mul2(iz2, P2[2*u]));
        U64 ob = fma2(gp2, G2[2*u+1], mul2(iz2, P2[2*u+1]));
        ulonglong2 w2; w2.x = oa; w2.y = ob;
        orow[u] = w2;
    }
}

// ---------------- launch ----------------
extern "C" void kernel_launch(void* const* d_in, const int* in_sizes, int n_in,
                              void* d_out, int out_size)
{
    (void)out_size;
    const float* qkv  = (const float*)d_in[0];
    const float* proj = (const float*)d_in[1];
    if (n_in >= 2 && in_sizes[0] < in_sizes[1]) {
        const float* tmp = qkv; qkv = proj; proj = tmp;
    }
    float* out = (float*)d_out;

    cudaFuncSetAttribute(k4_main, cudaFuncAttributeMaxDynamicSharedMemorySize,
                         SM5_FLOATS * (int)sizeof(float));

    dim3 grid(NC, Hc);
    k1_feat  <<<grid, 128>>>(qkv, proj);
    k2_kprime<<<grid, 128>>>(qkv);
    k3_scan  <<<Hc, 256>>>();
    k4_main  <<<grid, 256, SM5_FLOATS * (int)sizeof(float)>>>(qkv, proj, out);
}

// round 4
// speedup vs baseline: 1.2515x; 1.2515x over previous
#include <cuda_runtime.h>
#include <math.h>

// Problem constants (B=1)
#define Lc     2048
#define Hc     16
#define Dc     64
#define Mc     24
#define Wc     128
#define CHUNK  128
#define NC     16
#define SCALEc 0.125f
#define EPSc   1e-4f
#define DN     0.35355339059327373f   // sqrt(0.125)
#define LN24   3.1780538303479458f    // log(24)

typedef unsigned long long U64;

__device__ __forceinline__ U64 fma2(U64 a, U64 b, U64 c) {
    U64 d; asm("fma.rn.f32x2 %0, %1, %2, %3;" : "=l"(d) : "l"(a), "l"(b), "l"(c)); return d;
}
__device__ __forceinline__ U64 mul2(U64 a, U64 b) {
    U64 d; asm("mul.rn.f32x2 %0, %1, %2;" : "=l"(d) : "l"(a), "l"(b)); return d;
}
__device__ __forceinline__ U64 add2(U64 a, U64 b) {
    U64 d; asm("add.rn.f32x2 %0, %1, %2;" : "=l"(d) : "l"(a), "l"(b)); return d;
}
__device__ __forceinline__ U64 pack2(float x, float y) {
    U64 d; asm("mov.b64 %0, {%1,%2};" : "=l"(d)
               : "r"(__float_as_uint(x)), "r"(__float_as_uint(y))); return d;
}
__device__ __forceinline__ float hadd2(U64 a) {
    unsigned lo, hi; asm("mov.b64 {%0,%1}, %2;" : "=r"(lo), "=r"(hi) : "l"(a));
    return __uint_as_float(lo) + __uint_as_float(hi);
}
__device__ __forceinline__ void unpack2(float& x, float& y, U64 a) {
    unsigned lo, hi; asm("mov.b64 {%0,%1}, %2;" : "=r"(lo), "=r"(hi) : "l"(a));
    x = __uint_as_float(lo); y = __uint_as_float(hi);
}

#define CP_COMMIT() asm volatile("cp.async.commit_group;")
#define CP_WAIT(n)  asm volatile("cp.async.wait_group %0;" :: "n"(n))

// ---------------- scratch ----------------
__device__ float g_xdash[Hc * NC * Mc * CHUNK];
__device__ float g_xn[Hc * NC * CHUNK];
__device__ float g_kprime[Hc * Lc * Mc];
__device__ float g_chunkmax[Hc * NC];
__device__ float g_kstab[Hc];
__device__ float g_ksum [Hc * NC * Mc];
__device__ float g_kvsum[Hc * NC * Mc * Dc];
__device__ float g_kbase [Hc * NC * Mc];
__device__ float g_kvbase[Hc * NC * Mc * Dc];

// ---------------- kernel 1: key features + chunk max (unchanged) ------
__global__ void __launch_bounds__(128) k1_feat(const float* __restrict__ qkv,
                                               const float* __restrict__ proj)
{
    __shared__ float proj_s[Mc * Dc];
    __shared__ float red[128];
    const int c = blockIdx.x, h = blockIdx.y, t = threadIdx.x;
    const int hc = h * NC + c;

    for (int f = t; f < Mc * Dc / 4; f += 128)
        ((float4*)proj_s)[f] = ((const float4*)proj)[f];
    __syncthreads();

    const int l = c * CHUNK + t;
    float k[Dc];
    const float4* kr = (const float4*)(qkv + ((size_t)(l * 3 + 1) * Hc + h) * Dc);
#pragma unroll
    for (int dv = 0; dv < 16; dv++) {
        float4 x = kr[dv];
        k[4*dv] = x.x; k[4*dv+1] = x.y; k[4*dv+2] = x.z; k[4*dv+3] = x.w;
    }
    float xn = 0.f;
#pragma unroll
    for (int d = 0; d < Dc; d++) xn = fmaf(k[d], k[d], xn);
    g_xn[hc * CHUNK + t] = xn * 0.0625f;

    float mx = -3.4e38f;
#pragma unroll
    for (int m = 0; m < Mc; m++) {
        const float* pr = proj_s + m * Dc;
        float d0 = 0.f, d1 = 0.f, d2 = 0.f, d3 = 0.f;
#pragma unroll
        for (int d = 0; d < Dc; d += 4) {
            d0 = fmaf(pr[d  ], k[d  ], d0);
            d1 = fmaf(pr[d+1], k[d+1], d1);
            d2 = fmaf(pr[d+2], k[d+2], d2);
            d3 = fmaf(pr[d+3], k[d+3], d3);
        }
        float xd = ((d0 + d1) + (d2 + d3)) * DN;
        g_xdash[(hc * Mc + m) * CHUNK + t] = xd;
        mx = fmaxf(mx, xd);
    }
    red[t] = mx;
    __syncthreads();
    for (int s = 64; s > 0; s >>= 1) {
        if (t < s) red[t] = fmaxf(red[t], red[t + s]);
        __syncthreads();
    }
    if (t == 0) g_chunkmax[hc] = red[0];
}

// ---------------- kernel 2: k' + per-chunk sums (unchanged) ------------
__global__ void __launch_bounds__(128) k2_kprime(const float* __restrict__ qkv)
{
    __shared__ float vbuf[CHUNK * Dc];
    __shared__ float kp_s[CHUNK * 25];
    const int c = blockIdx.x, h = blockIdx.y, t = threadIdx.x;
    const int hc = h * NC + c;

    float kstab = -3.4e38f;
#pragma unroll
    for (int cc = 0; cc < NC; cc++) kstab = fmaxf(kstab, g_chunkmax[h * NC + cc]);
    if (c == 0 && t == 0) g_kstab[h] = kstab;

    const int tilebase = c * CHUNK;
    for (int f = t; f < CHUNK * 16; f += 128) {
        int r = f >> 4, dv = f & 15;
        ((float4*)vbuf)[f] =
            ((const float4*)(qkv + ((size_t)((tilebase + r) * 3 + 2) * Hc + h) * Dc))[dv];
    }

    const float xn = g_xn[hc * CHUNK + t];
    const int l = tilebase + t;
    float* kpo = g_kprime + ((size_t)h * Lc + l) * Mc;
#pragma unroll
    for (int m = 0; m < Mc; m++) {
        float xd = g_xdash[(hc * Mc + m) * CHUNK + t];
        float val = __expf(xd - xn - kstab) + EPSc;
        kp_s[t * 25 + m] = val;
        kpo[m] = val;
    }
    __syncthreads();

    float4* kvo4 = (float4*)(g_kvsum + (size_t)hc * Mc * Dc);
    const float4* vb4 = (const float4*)vbuf;
#pragma unroll
    for (int grp = 0; grp < 3; grp++) {
        int o = t + 128 * grp;
        int m = o >> 4, d4 = o & 15;
        float4 a = make_float4(0.f, 0.f, 0.f, 0.f);
        for (int row = 0; row < CHUNK; row++) {
            float kp = kp_s[row * 25 + m];
            float4 v = vb4[row * 16 + d4];
            a.x = fmaf(kp, v.x, a.x);
            a.y = fmaf(kp, v.y, a.y);
            a.z = fmaf(kp, v.z, a.z);
            a.w = fmaf(kp, v.w, a.w);
        }
        kvo4[o] = a;
    }
    if (t < Mc) {
        float a = 0.f;
        for (int row = 0; row < CHUNK; row++) a += kp_s[row * 25 + t];
        g_ksum[hc * Mc + t] = a;
    }
}

// ---------------- kernel 3: exclusive scan (unchanged) -----------------
__global__ void __launch_bounds__(256) k3_scan()
{
    const int h = blockIdx.x, t = threadIdx.x;
    for (int e = t; e < Mc * Dc; e += 256) {
        float run = 0.f;
#pragma unroll
        for (int c = 0; c < NC; c++) {
            size_t idx = ((size_t)(h * NC + c)) * Mc * Dc + e;
            g_kvbase[idx] = run;
            run += g_kvsum[idx];
        }
    }
    if (t < Mc) {
        float run = 0.f;
#pragma unroll
        for (int c = 0; c < NC; c++) {
            int idx = (h * NC + c) * Mc + t;
            g_kbase[idx] = run;
            run += g_ksum[idx];
        }
    }
}

// ---------------- kernel 4: fused attention, f32x2, cp.async V ring ----------
// smem (floats): K 256*64=16384 @0 | kp 256*24=6144 @16384 | proj 1536 @22528
//                | ring 4w*4slots*2rows*64 = 2048 @24064 | total 26112 fl = 102 KB
#define OFF_K    0
#define OFF_KP   16384
#define OFF_PROJ 22528
#define OFF_RING 24064
#define SM4_FLOATS 26112

__device__ __forceinline__ float sdot64(const float* krow, const U64* q2) {
    const ulonglong2* kr = (const ulonglong2*)krow;
    U64 a0, a1, a2, a3;
    {
        ulonglong2 x = kr[0]; a0 = mul2(q2[0], x.x); a1 = mul2(q2[1], x.y);
        ulonglong2 y = kr[1]; a2 = mul2(q2[2], y.x); a3 = mul2(q2[3], y.y);
    }
#pragma unroll
    for (int u = 2; u < 16; u += 2) {
        ulonglong2 x = kr[u];     a0 = fma2(q2[2*u],   x.x, a0); a1 = fma2(q2[2*u+1], x.y, a1);
        ulonglong2 y = kr[u + 1]; a2 = fma2(q2[2*u+2], y.x, a2); a3 = fma2(q2[2*u+3], y.y, a3);
    }
    return hadd2(add2(add2(a0, a1), add2(a2, a3)));
}

__device__ __forceinline__ float gdot24(const float* kprow, const U64* qp2) {
    const ulonglong2* pr = (const ulonglong2*)kprow;
    ulonglong2 y0 = pr[0], y1 = pr[1], y2 = pr[2];
    U64 g0 = mul2(qp2[0], y0.x), g1 = mul2(qp2[1], y0.y);
    g0 = fma2(qp2[2], y1.x, g0);  g1 = fma2(qp2[3], y1.y, g1);
    g0 = fma2(qp2[4], y2.x, g0);  g1 = fma2(qp2[5], y2.y, g1);
    ulonglong2 y3 = pr[3], y4 = pr[4], y5 = pr[5];
    g0 = fma2(qp2[6],  y3.x, g0); g1 = fma2(qp2[7],  y3.y, g1);
    g0 = fma2(qp2[8],  y4.x, g0); g1 = fma2(qp2[9],  y4.y, g1);
    g0 = fma2(qp2[10], y5.x, g0); g1 = fma2(qp2[11], y5.y, g1);
    return hadd2(add2(g0, g1));
}

__device__ __forceinline__ void vacc64(U64 c2, const float* vrow, U64* o2) {
    const ulonglong2* vr = (const ulonglong2*)vrow;
#pragma unroll
    for (int u = 0; u < 16; u++) {
        ulonglong2 x = vr[u];
        o2[2*u]   = fma2(c2, x.x, o2[2*u]);
        o2[2*u+1] = fma2(c2, x.y, o2[2*u+1]);
    }
}

// stage 2 V rows (global key indices ra, rb) into ring slot; one LDGSTS inst
__device__ __forceinline__ void stage2v(const float* __restrict__ qkv, int h,
                                        unsigned ringw_u32, int slot,
                                        int ra, int rb, int lane)
{
    int row = (lane < 16) ? ra : rb;
    const float* src = qkv + ((size_t)(row * 3 + 2) * Hc + h) * Dc + (lane & 15) * 4;
    unsigned dst = ringw_u32 + (unsigned)(slot * 512 + ((lane >> 4) * 256) + (lane & 15) * 16);
    asm volatile("cp.async.cg.shared.global [%0], [%1], 16;" :: "r"(dst), "l"(src));
}

__global__ void __launch_bounds__(128, 2) k4_main(const float* __restrict__ qkv,
                                                  const float* __restrict__ proj,
                                                  float* __restrict__ out)
{
    extern __shared__ float sm[];
    float* K_s    = sm + OFF_K;
    float* kp_s   = sm + OFF_KP;
    float* proj_s = sm + OFF_PROJ;
    float* ring   = sm + OFF_RING;

    const int c = blockIdx.x, h = blockIdx.y, t = threadIdx.x;
    const int warp = t >> 5, lane = t & 31;
    const int cstart = c * CHUNK;
    const int i = cstart + t;
    const int tilebase = (c > 0) ? (c - 1) * CHUNK : 0;
    const int nkeys    = (c > 0) ? 256 : 128;
    const int cb = (c > 0) ? 128 : 0;            // smem row offset of current chunk

    // ---- cooperative tile load ----
    for (int f = t; f < nkeys * 16; f += 128) {
        int r = f >> 4, dv = f & 15;
        ((float4*)K_s)[r * 16 + dv] =
            ((const float4*)(qkv + ((size_t)((tilebase + r) * 3 + 1) * Hc + h) * Dc))[dv];
    }
    {
        const float4* kpsrc = (const float4*)(g_kprime + ((size_t)h * Lc + tilebase) * Mc);
        for (int f = t; f < nkeys * 6; f += 128) ((float4*)kp_s)[f] = kpsrc[f];
        for (int f = t; f < 384; f += 128) ((float4*)proj_s)[f] = ((const float4*)proj)[f];
    }
    __syncthreads();

    // ---- query features (f32x2, full dims in-thread) ----
    U64 q2[32];
    {
        const ulonglong2* qr = (const ulonglong2*)(qkv + ((size_t)(i * 3) * Hc + h) * Dc);
#pragma unroll
        for (int u = 0; u < 16; u++) { ulonglong2 x = qr[u]; q2[2*u] = x.x; q2[2*u+1] = x.y; }
    }
    float xn;
    {
        U64 a0 = mul2(q2[0], q2[0]), a1 = mul2(q2[1], q2[1]);
        U64 a2 = mul2(q2[2], q2[2]), a3 = mul2(q2[3], q2[3]);
#pragma unroll
        for (int u = 4; u < 32; u += 4) {
            a0 = fma2(q2[u],   q2[u],   a0);
            a1 = fma2(q2[u+1], q2[u+1], a1);
            a2 = fma2(q2[u+2], q2[u+2], a2);
            a3 = fma2(q2[u+3], q2[u+3], a3);
        }
        xn = hadd2(add2(add2(a0, a1), add2(a2, a3))) * 0.0625f;
    }
    float xd[Mc];
    float qstab = -3.4e38f;
#pragma unroll
    for (int m = 0; m < Mc; m++) {
        float p = sdot64(proj_s + m * Dc, q2);
        xd[m] = p * DN;
        qstab = fmaxf(qstab, xd[m]);
    }
    U64 qp2[12];
#pragma unroll
    for (int e = 0; e < 12; e++) {
        float a = __expf(xd[2*e]   - qstab) + EPSc;
        float b = __expf(xd[2*e+1] - qstab) + EPSc;
        qp2[e] = pack2(a, b);
    }

    const float kstab = __ldg(&g_kstab[h]);
    const float gs = qstab - xn + kstab - LN24;
    float kbdot = 0.f;
    {
        const float* kb = g_kbase + (h * NC + c) * Mc;
#pragma unroll
        for (int e = 0; e < 12; e++) {
            float a, b; unpack2(a, b, qp2[e]);
            kbdot = fmaf(a, __ldg(kb + 2*e),     kbdot);
            kbdot = fmaf(b, __ldg(kb + 2*e + 1), kbdot);
        }
    }

    // ---- pass 1: Z, Asc (no barriers; warps independent) ----
    float Z = 0.f, AscP = 0.f, AscC = 0.f;
    const int j0 = 32 * warp;
    if (c > 0) {
        for (int jr = j0; jr < 128; jr++) {
            float s = sdot64(K_s + jr * Dc, q2) * SCALEc;
            float g = gdot24(kp_s + jr * Mc, qp2);
            if (jr >= t) { Z += __expf(s); AscP += g; }
        }
    }
    {
        const int jend = j0 + 32;
        for (int jc = 0; jc < jend; jc++) {
            float s = sdot64(K_s + (cb + jc) * Dc, q2) * SCALEc;
            float g = gdot24(kp_s + (cb + jc) * Mc, qp2);
            if (jc <= t) { Z += __expf(s); AscC += g; }
        }
    }

    // ---- normalization scalars ----
    const float Asc = 0.875f * AscC - 0.125f * AscP;
    const float lse = __logf(Z);
    const float gln = __logf(fmaxf(kbdot + Asc, 1e-24f)) + gs;
    float a_ = fmaxf(lse, gln), b_ = fminf(lse, gln);
    const float lnorm = a_ + log1pf(__expf(b_ - a_));
    const float gps  = __expf(gs - lnorm);
    const float invZ = 1.f / Z;
    const float gpsP = -0.125f * gps;
    const float gpsC =  0.875f * gps;

    // ---- pass 2: output accumulation with cp.async V ring ----
    U64 o2[32];
#pragma unroll
    for (int u = 0; u < 32; u++) o2[u] = 0ULL;

    const unsigned ringw_u32 =
        (unsigned)__cvta_generic_to_shared(ring + warp * 512);
    const float* ringw = ring + warp * 512;

    if (c > 0) {
        const int nbat = (128 - j0) >> 1;
        // prologue: stage batches 0..2
#pragma unroll
        for (int p = 0; p < 3; p++) {
            int ra = j0 + 2*p;     if (ra > 127) ra = 127;
            int rb = j0 + 2*p + 1; if (rb > 127) rb = 127;
            stage2v(qkv, h, ringw_u32, p & 3, tilebase + ra, tilebase + rb, lane);
            CP_COMMIT();
        }
        for (int b = 0; b < nbat; b++) {
            int sp = b + 3;
            int ra = j0 + 2*sp;     if (ra > 127) ra = 127;
            int rb = j0 + 2*sp + 1; if (rb > 127) rb = 127;
            stage2v(qkv, h, ringw_u32, sp & 3, tilebase + ra, tilebase + rb, lane);
            CP_COMMIT();
            CP_WAIT(3);
            __syncwarp();
            const float* vb = ringw + (b & 3) * 128;
#pragma unroll
            for (int e = 0; e < 2; e++) {
                const int jr = j0 + 2*b + e;
                float s = sdot64(K_s + jr * Dc, q2) * SCALEc;
                float g = gdot24(kp_s + jr * Mc, qp2);
                float coef = (jr >= t) ? fmaf(invZ, __expf(s), gpsP * g) : 0.f;
                vacc64(pack2(coef, coef), vb + e * 64, o2);
            }
        }
        CP_WAIT(0);
        __syncwarp();
    }
    {
        const int jend = j0 + 32;           // even
        const int nbat = jend >> 1;
#pragma unroll
        for (int p = 0; p < 3; p++) {
            int ra = 2*p;     if (ra > jend - 1) ra = jend - 1;
            int rb = 2*p + 1; if (rb > jend - 1) rb = jend - 1;
            stage2v(qkv, h, ringw_u32, p & 3, cstart + ra, cstart + rb, lane);
            CP_COMMIT();
        }
        for (int b = 0; b < nbat; b++) {
            int sp = b + 3;
            int ra = 2*sp;     if (ra > jend - 1) ra = jend - 1;
            int rb = 2*sp + 1; if (rb > jend - 1) rb = jend - 1;
            stage2v(qkv, h, ringw_u32, sp & 3, cstart + ra, cstart + rb, lane);
            CP_COMMIT();
            CP_WAIT(3);
            __syncwarp();
            const float* vb = ringw + (b & 3) * 128;
#pragma unroll
            for (int e = 0; e < 2; e++) {
                const int jc = 2*b + e;
                float s = sdot64(K_s + (cb + jc) * Dc, q2) * SCALEc;
                float g = gdot24(kp_s + (cb + jc) * Mc, qp2);
                float coef = (jc <= t) ? fmaf(invZ, __expf(s), gpsC * g) : 0.f;
                vacc64(pack2(coef, coef), vb + e * 64, o2);
            }
        }
        CP_WAIT(0);
        __syncwarp();
    }

    // ---- epilogue: o += gps * (q' . KVbase) ----
    {
        const float* kvb = g_kvbase + ((size_t)(h * NC + c)) * Mc * Dc;
#pragma unroll
        for (int e = 0; e < 12; e++) {
            float qa, qb; unpack2(qa, qb, qp2[e]);
            U64 ca = pack2(gps * qa, gps * qa);
            U64 cb2 = pack2(gps * qb, gps * qb);
            const ulonglong2* r0 = (const ulonglong2*)(kvb + (2*e) * Dc);
            const ulonglong2* r1 = (const ulonglong2*)(kvb + (2*e + 1) * Dc);
#pragma unroll
            for (int u = 0; u < 16; u++) {
                ulonglong2 x0 = __ldg(&r0[u]);
                ulonglong2 x1 = __ldg(&r1[u]);
                o2[2*u]   = fma2(ca,  x0.x, o2[2*u]);
                o2[2*u+1] = fma2(ca,  x0.y, o2[2*u+1]);
                o2[2*u]   = fma2(cb2, x1.x, o2[2*u]);
                o2[2*u+1] = fma2(cb2, x1.y, o2[2*u+1]);
            }
        }
    }

    ulonglong2* orow = (ulonglong2*)(out + ((size_t)i * Hc + h) * Dc);
#pragma unroll
    for (int u = 0; u < 16; u++) {
        ulonglong2 w2; w2.x = o2[2*u]; w2.y = o2[2*u+1];
        orow[u] = w2;
    }
}

// ---------------- launch ----------------
extern "C" void kernel_launch(void* const* d_in, const int* in_sizes, int n_in,
                              void* d_out, int out_size)
{
    (void)out_size;
    const float* qkv  = (const float*)d_in[0];
    const float* proj = (const float*)d_in[1];
    if (n_in >= 2 && in_sizes[0] < in_sizes[1]) {
        const float* tmp = qkv; qkv = proj; proj = tmp;
    }
    float* out = (float*)d_out;

    cudaFuncSetAttribute(k4_main, cudaFuncAttributeMaxDynamicSharedMemorySize,
                         SM4_FLOATS * (int)sizeof(float));

    dim3 grid(NC, Hc);
    k1_feat  <<<grid, 128>>>(qkv, proj);
    k2_kprime<<<grid, 128>>>(qkv);
    k3_scan  <<<Hc, 256>>>();
    k4_main  <<<grid, 128, SM4_FLOATS * (int)sizeof(float)>>>(qkv, proj, out);
}

// round 5
// speedup vs baseline: 1.8386x; 1.4691x over previous
#include <cuda_runtime.h>
#include <math.h>

// Problem constants (B=1)
#define Lc     2048
#define Hc     16
#define Dc     64
#define Mc     24
#define Wc     128
#define CHUNK  128
#define NC     16
#define SCALEc 0.125f
#define EPSc   1e-4f
#define DN     0.35355339059327373f   // sqrt(0.125)
#define LN24   3.1780538303479458f    // log(24)

typedef unsigned long long U64;

__device__ __forceinline__ U64 fma2(U64 a, U64 b, U64 c) {
    U64 d; asm("fma.rn.f32x2 %0, %1, %2, %3;" : "=l"(d) : "l"(a), "l"(b), "l"(c)); return d;
}
__device__ __forceinline__ U64 mul2(U64 a, U64 b) {
    U64 d; asm("mul.rn.f32x2 %0, %1, %2;" : "=l"(d) : "l"(a), "l"(b)); return d;
}
__device__ __forceinline__ U64 add2(U64 a, U64 b) {
    U64 d; asm("add.rn.f32x2 %0, %1, %2;" : "=l"(d) : "l"(a), "l"(b)); return d;
}
__device__ __forceinline__ U64 pack2(float x, float y) {
    U64 d; asm("mov.b64 %0, {%1,%2};" : "=l"(d)
               : "r"(__float_as_uint(x)), "r"(__float_as_uint(y))); return d;
}
__device__ __forceinline__ float hadd2(U64 a) {
    unsigned lo, hi; asm("mov.b64 {%0,%1}, %2;" : "=r"(lo), "=r"(hi) : "l"(a));
    return __uint_as_float(lo) + __uint_as_float(hi);
}
__device__ __forceinline__ void unpack2(float& x, float& y, U64 a) {
    unsigned lo, hi; asm("mov.b64 {%0,%1}, %2;" : "=r"(lo), "=r"(hi) : "l"(a));
    x = __uint_as_float(lo); y = __uint_as_float(hi);
}

#define CP_COMMIT() asm volatile("cp.async.commit_group;")
#define CP_WAIT(n)  asm volatile("cp.async.wait_group %0;" :: "n"(n))

// ---------------- scratch ----------------
__device__ float g_xdash[Hc * NC * Mc * CHUNK];
__device__ float g_xn[Hc * NC * CHUNK];
__device__ float g_kprime[Hc * Lc * Mc];
__device__ float g_chunkmax[Hc * NC];
__device__ float g_kstab[Hc];
__device__ float g_ksum [Hc * NC * Mc];
__device__ float g_kvsum[Hc * NC * Mc * Dc];

// ---------------- kernel 1: key features + chunk max (unchanged) ------
__global__ void __launch_bounds__(128) k1_feat(const float* __restrict__ qkv,
                                               const float* __restrict__ proj)
{
    __shared__ float proj_s[Mc * Dc];
    __shared__ float red[128];
    const int c = blockIdx.x, h = blockIdx.y, t = threadIdx.x;
    const int hc = h * NC + c;

    for (int f = t; f < Mc * Dc / 4; f += 128)
        ((float4*)proj_s)[f] = ((const float4*)proj)[f];
    __syncthreads();

    const int l = c * CHUNK + t;
    float k[Dc];
    const float4* kr = (const float4*)(qkv + ((size_t)(l * 3 + 1) * Hc + h) * Dc);
#pragma unroll
    for (int dv = 0; dv < 16; dv++) {
        float4 x = kr[dv];
        k[4*dv] = x.x; k[4*dv+1] = x.y; k[4*dv+2] = x.z; k[4*dv+3] = x.w;
    }
    float xn = 0.f;
#pragma unroll
    for (int d = 0; d < Dc; d++) xn = fmaf(k[d], k[d], xn);
    g_xn[hc * CHUNK + t] = xn * 0.0625f;

    float mx = -3.4e38f;
#pragma unroll
    for (int m = 0; m < Mc; m++) {
        const float* pr = proj_s + m * Dc;
        float d0 = 0.f, d1 = 0.f, d2 = 0.f, d3 = 0.f;
#pragma unroll
        for (int d = 0; d < Dc; d += 4) {
            d0 = fmaf(pr[d  ], k[d  ], d0);
            d1 = fmaf(pr[d+1], k[d+1], d1);
            d2 = fmaf(pr[d+2], k[d+2], d2);
            d3 = fmaf(pr[d+3], k[d+3], d3);
        }
        float xd = ((d0 + d1) + (d2 + d3)) * DN;
        g_xdash[(hc * Mc + m) * CHUNK + t] = xd;
        mx = fmaxf(mx, xd);
    }
    red[t] = mx;
    __syncthreads();
    for (int s = 64; s > 0; s >>= 1) {
        if (t < s) red[t] = fmaxf(red[t], red[t + s]);
        __syncthreads();
    }
    if (t == 0) g_chunkmax[hc] = red[0];
}

// ---------------- kernel 2: k' + per-chunk sums (unchanged) ------------
__global__ void __launch_bounds__(128) k2_kprime(const float* __restrict__ qkv)
{
    __shared__ float vbuf[CHUNK * Dc];
    __shared__ float kp_s[CHUNK * 25];
    const int c = blockIdx.x, h = blockIdx.y, t = threadIdx.x;
    const int hc = h * NC + c;

    float kstab = -3.4e38f;
#pragma unroll
    for (int cc = 0; cc < NC; cc++) kstab = fmaxf(kstab, g_chunkmax[h * NC + cc]);
    if (c == 0 && t == 0) g_kstab[h] = kstab;

    const int tilebase = c * CHUNK;
    for (int f = t; f < CHUNK * 16; f += 128) {
        int r = f >> 4, dv = f & 15;
        ((float4*)vbuf)[f] =
            ((const float4*)(qkv + ((size_t)((tilebase + r) * 3 + 2) * Hc + h) * Dc))[dv];
    }

    const float xn = g_xn[hc * CHUNK + t];
    const int l = tilebase + t;
    float* kpo = g_kprime + ((size_t)h * Lc + l) * Mc;
#pragma unroll
    for (int m = 0; m < Mc; m++) {
        float xd = g_xdash[(hc * Mc + m) * CHUNK + t];
        float val = __expf(xd - xn - kstab) + EPSc;
        kp_s[t * 25 + m] = val;
        kpo[m] = val;
    }
    __syncthreads();

    float4* kvo4 = (float4*)(g_kvsum + (size_t)hc * Mc * Dc);
    const float4* vb4 = (const float4*)vbuf;
#pragma unroll
    for (int grp = 0; grp < 3; grp++) {
        int o = t + 128 * grp;
        int m = o >> 4, d4 = o & 15;
        float4 a = make_float4(0.f, 0.f, 0.f, 0.f);
        for (int row = 0; row < CHUNK; row++) {
            float kp = kp_s[row * 25 + m];
            float4 v = vb4[row * 16 + d4];
            a.x = fmaf(kp, v.x, a.x);
            a.y = fmaf(kp, v.y, a.y);
            a.z = fmaf(kp, v.z, a.z);
            a.w = fmaf(kp, v.w, a.w);
        }
        kvo4[o] = a;
    }
    if (t < Mc) {
        float a = 0.f;
        for (int row = 0; row < CHUNK; row++) a += kp_s[row * 25 + t];
        g_ksum[hc * Mc + t] = a;
    }
}

// ---------------- kernel 4: fused attention ----------
// smem (floats): K 16384 @0 | kp 6144 @16384 | proj 1536 @22528
//   | kvb 1536 @24064 | kb 32 @25600 | ring 2048 @25632 | total 27680 = 108.1 KB
#define OFF_K    0
#define OFF_KP   16384
#define OFF_PROJ 22528
#define OFF_KVB  24064
#define OFF_KB   25600
#define OFF_RING 25632
#define SM4_FLOATS 27680

__device__ __forceinline__ float sdot64(const float* krow, const U64* q2) {
    const ulonglong2* kr = (const ulonglong2*)krow;
    U64 a0, a1, a2, a3;
    {
        ulonglong2 x = kr[0]; a0 = mul2(q2[0], x.x); a1 = mul2(q2[1], x.y);
        ulonglong2 y = kr[1]; a2 = mul2(q2[2], y.x); a3 = mul2(q2[3], y.y);
    }
#pragma unroll
    for (int u = 2; u < 16; u += 2) {
        ulonglong2 x = kr[u];     a0 = fma2(q2[2*u],   x.x, a0); a1 = fma2(q2[2*u+1], x.y, a1);
        ulonglong2 y = kr[u + 1]; a2 = fma2(q2[2*u+2], y.x, a2); a3 = fma2(q2[2*u+3], y.y, a3);
    }
    return hadd2(add2(add2(a0, a1), add2(a2, a3)));
}

__device__ __forceinline__ float gdot24(const float* kprow, const U64* qp2) {
    const ulonglong2* pr = (const ulonglong2*)kprow;
    ulonglong2 y0 = pr[0], y1 = pr[1], y2 = pr[2];
    U64 g0 = mul2(qp2[0], y0.x), g1 = mul2(qp2[1], y0.y);
    g0 = fma2(qp2[2], y1.x, g0);  g1 = fma2(qp2[3], y1.y, g1);
    g0 = fma2(qp2[4], y2.x, g0);  g1 = fma2(qp2[5], y2.y, g1);
    ulonglong2 y3 = pr[3], y4 = pr[4], y5 = pr[5];
    g0 = fma2(qp2[6],  y3.x, g0); g1 = fma2(qp2[7],  y3.y, g1);
    g0 = fma2(qp2[8],  y4.x, g0); g1 = fma2(qp2[9],  y4.y, g1);
    g0 = fma2(qp2[10], y5.x, g0); g1 = fma2(qp2[11], y5.y, g1);
    return hadd2(add2(g0, g1));
}

__device__ __forceinline__ void vacc64(U64 c2, const float* vrow, U64* o2) {
    const ulonglong2* vr = (const ulonglong2*)vrow;
#pragma unroll
    for (int u = 0; u < 16; u++) {
        ulonglong2 x = vr[u];
        o2[2*u]   = fma2(c2, x.x, o2[2*u]);
        o2[2*u+1] = fma2(c2, x.y, o2[2*u+1]);
    }
}

// stage 2 V rows (global key indices ra, rb) into ring slot; one LDGSTS inst
__device__ __forceinline__ void stage2v(const float* __restrict__ qkv, int h,
                                        unsigned ringw_u32, int slot,
                                        int ra, int rb, int lane)
{
    int row = (lane < 16) ? ra : rb;
    const float* src = qkv + ((size_t)(row * 3 + 2) * Hc + h) * Dc + (lane & 15) * 4;
    unsigned dst = ringw_u32 + (unsigned)(slot * 512 + ((lane >> 4) * 256) + (lane & 15) * 16);
    asm volatile("cp.async.cg.shared.global [%0], [%1], 16;" :: "r"(dst), "l"(src));
}

__global__ void __launch_bounds__(128, 2) k4_main(const float* __restrict__ qkv,
                                                  const float* __restrict__ proj,
                                                  float* __restrict__ out)
{
    extern __shared__ float sm[];
    float* K_s    = sm + OFF_K;
    float* kp_s   = sm + OFF_KP;
    float* proj_s = sm + OFF_PROJ;
    float* kvb_s  = sm + OFF_KVB;
    float* kb_s   = sm + OFF_KB;
    float* ring   = sm + OFF_RING;

    const int c = blockIdx.x, h = blockIdx.y, t = threadIdx.x;
    const int warp = t >> 5, lane = t & 31;
    const int cstart = c * CHUNK;
    const int i = cstart + t;
    const int tilebase = (c > 0) ? (c - 1) * CHUNK : 0;
    const int nkeys    = (c > 0) ? 256 : 128;
    const int cb = (c > 0) ? 128 : 0;            // smem row offset of current chunk

    // ---- cooperative tile load ----
    for (int f = t; f < nkeys * 16; f += 128) {
        int r = f >> 4, dv = f & 15;
        ((float4*)K_s)[r * 16 + dv] =
            ((const float4*)(qkv + ((size_t)((tilebase + r) * 3 + 1) * Hc + h) * Dc))[dv];
    }
    {
        const float4* kpsrc = (const float4*)(g_kprime + ((size_t)h * Lc + tilebase) * Mc);
        for (int f = t; f < nkeys * 6; f += 128) ((float4*)kp_s)[f] = kpsrc[f];
        for (int f = t; f < 384; f += 128) ((float4*)proj_s)[f] = ((const float4*)proj)[f];
    }
    // ---- inline prefix-scan (replaces old k3): kvb_s, kb_s ----
#pragma unroll
    for (int g = 0; g < 3; g++) {
        int f = t + 128 * g;
        float4 a = make_float4(0.f, 0.f, 0.f, 0.f);
        for (int cc = 0; cc < c; cc++) {
            float4 x = __ldg((const float4*)g_kvsum + (size_t)(h * NC + cc) * 384 + f);
            a.x += x.x; a.y += x.y; a.z += x.z; a.w += x.w;
        }
        ((float4*)kvb_s)[f] = a;
    }
    if (t < Mc) {
        float a = 0.f;
        for (int cc = 0; cc < c; cc++) a += __ldg(&g_ksum[(h * NC + cc) * Mc + t]);
        kb_s[t] = a;
    }
    __syncthreads();

    // ---- query features (f32x2, full dims in-thread) ----
    U64 q2[32];
    {
        const ulonglong2* qr = (const ulonglong2*)(qkv + ((size_t)(i * 3) * Hc + h) * Dc);
#pragma unroll
        for (int u = 0; u < 16; u++) { ulonglong2 x = qr[u]; q2[2*u] = x.x; q2[2*u+1] = x.y; }
    }
    float xn;
    {
        U64 a0 = mul2(q2[0], q2[0]), a1 = mul2(q2[1], q2[1]);
        U64 a2 = mul2(q2[2], q2[2]), a3 = mul2(q2[3], q2[3]);
#pragma unroll
        for (int u = 4; u < 32; u += 4) {
            a0 = fma2(q2[u],   q2[u],   a0);
            a1 = fma2(q2[u+1], q2[u+1], a1);
            a2 = fma2(q2[u+2], q2[u+2], a2);
            a3 = fma2(q2[u+3], q2[u+3], a3);
        }
        xn = hadd2(add2(add2(a0, a1), add2(a2, a3))) * 0.0625f;
    }
    float xd[Mc];
    float qstab = -3.4e38f;
#pragma unroll
    for (int m = 0; m < Mc; m++) {
        float p = sdot64(proj_s + m * Dc, q2);
        xd[m] = p * DN;
        qstab = fmaxf(qstab, xd[m]);
    }
    U64 qp2[12];
#pragma unroll
    for (int e = 0; e < 12; e++) {
        float a = __expf(xd[2*e]   - qstab) + EPSc;
        float b = __expf(xd[2*e+1] - qstab) + EPSc;
        qp2[e] = pack2(a, b);
    }

    const float kstab = __ldg(&g_kstab[h]);
    const float gs = qstab - xn + kstab - LN24;
    float kbdot = 0.f;
#pragma unroll
    for (int e = 0; e < 12; e++) {
        float a, b; unpack2(a, b, qp2[e]);
        kbdot = fmaf(a, kb_s[2*e],     kbdot);
        kbdot = fmaf(b, kb_s[2*e + 1], kbdot);
    }

    // ---- pass 1: Z, Asc; cache (exp(s), g) per key in local array ----
    float2 sg[160];
    int idx = 0;
    float Z = 0.f, AscP = 0.f, AscC = 0.f;
    const int j0 = 32 * warp;
    if (c > 0) {
#pragma unroll 1
        for (int jr = j0; jr < 128; jr++) {
            float s = sdot64(K_s + jr * Dc, q2) * SCALEc;
            float g = gdot24(kp_s + jr * Mc, qp2);
            float es = (jr >= t) ? __expf(s) : 0.f;
            float gg = (jr >= t) ? g : 0.f;
            Z += es; AscP += gg;
            sg[idx++] = make_float2(es, gg);
        }
    }
    {
        const int jend = j0 + 32;
#pragma unroll 1
        for (int jc = 0; jc < jend; jc++) {
            float s = sdot64(K_s + (cb + jc) * Dc, q2) * SCALEc;
            float g = gdot24(kp_s + (cb + jc) * Mc, qp2);
            float es = (jc <= t) ? __expf(s) : 0.f;
            float gg = (jc <= t) ? g : 0.f;
            Z += es; AscC += gg;
            sg[idx++] = make_float2(es, gg);
        }
    }

    // ---- normalization scalars ----
    const float Asc = 0.875f * AscC - 0.125f * AscP;
    const float lse = __logf(Z);
    const float gln = __logf(fmaxf(kbdot + Asc, 1e-24f)) + gs;
    float a_ = fmaxf(lse, gln), b_ = fminf(lse, gln);
    const float lnorm = a_ + log1pf(__expf(b_ - a_));
    const float gps  = __expf(gs - lnorm);
    const float invZ = 1.f / Z;
    const float gpsP = -0.125f * gps;
    const float gpsC =  0.875f * gps;

    // ---- pass 2: output accumulation with cp.async V ring + cached coefs ----
    U64 o2[32];
#pragma unroll
    for (int u = 0; u < 32; u++) o2[u] = 0ULL;

    const unsigned ringw_u32 =
        (unsigned)__cvta_generic_to_shared(ring + warp * 512);
    const float* ringw = ring + warp * 512;
    int idx2 = 0;

    if (c > 0) {
        const int nbat = (128 - j0) >> 1;
#pragma unroll
        for (int p = 0; p < 3; p++) {
            int ra = j0 + 2*p;     if (ra > 127) ra = 127;
            int rb = j0 + 2*p + 1; if (rb > 127) rb = 127;
            stage2v(qkv, h, ringw_u32, p & 3, tilebase + ra, tilebase + rb, lane);
            CP_COMMIT();
        }
#pragma unroll 1
        for (int b = 0; b < nbat; b++) {
            int sp = b + 3;
            int ra = j0 + 2*sp;     if (ra > 127) ra = 127;
            int rb = j0 + 2*sp + 1; if (rb > 127) rb = 127;
            stage2v(qkv, h, ringw_u32, sp & 3, tilebase + ra, tilebase + rb, lane);
            CP_COMMIT();
            CP_WAIT(3);
            __syncwarp();
            const float* vb = ringw + (b & 3) * 128;
#pragma unroll
            for (int e = 0; e < 2; e++) {
                float2 sgv = sg[idx2++];
                float coef = fmaf(invZ, sgv.x, gpsP * sgv.y);
                vacc64(pack2(coef, coef), vb + e * 64, o2);
            }
        }
        CP_WAIT(0);
        __syncwarp();
    }
    {
        const int jend = j0 + 32;           // even
        const int nbat = jend >> 1;
#pragma unroll
        for (int p = 0; p < 3; p++) {
            int ra = 2*p;     if (ra > jend - 1) ra = jend - 1;
            int rb = 2*p + 1; if (rb > jend - 1) rb = jend - 1;
            stage2v(qkv, h, ringw_u32, p & 3, cstart + ra, cstart + rb, lane);
            CP_COMMIT();
        }
#pragma unroll 1
        for (int b = 0; b < nbat; b++) {
            int sp = b + 3;
            int ra = 2*sp;     if (ra > jend - 1) ra = jend - 1;
            int rb = 2*sp + 1; if (rb > jend - 1) rb = jend - 1;
            stage2v(qkv, h, ringw_u32, sp & 3, cstart + ra, cstart + rb, lane);
            CP_COMMIT();
            CP_WAIT(3);
            __syncwarp();
            const float* vb = ringw + (b & 3) * 128;
#pragma unroll
            for (int e = 0; e < 2; e++) {
                float2 sgv = sg[idx2++];
                float coef = fmaf(invZ, sgv.x, gpsC * sgv.y);
                vacc64(pack2(coef, coef), vb + e * 64, o2);
            }
        }
        CP_WAIT(0);
        __syncwarp();
    }

    // ---- epilogue: o += gps * (q' . KVbase), KVbase from smem ----
#pragma unroll
    for (int e = 0; e < 12; e++) {
        float qa, qb; unpack2(qa, qb, qp2[e]);
        U64 ca  = pack2(gps * qa, gps * qa);
        U64 cb2 = pack2(gps * qb, gps * qb);
        const ulonglong2* r0 = (const ulonglong2*)(kvb_s + (2*e) * Dc);
        const ulonglong2* r1 = (const ulonglong2*)(kvb_s + (2*e + 1) * Dc);
#pragma unroll
        for (int u = 0; u < 16; u++) {
            ulonglong2 x0 = r0[u];
            ulonglong2 x1 = r1[u];
            o2[2*u]   = fma2(ca,  x0.x, o2[2*u]);
            o2[2*u+1] = fma2(ca,  x0.y, o2[2*u+1]);
            o2[2*u]   = fma2(cb2, x1.x, o2[2*u]);
            o2[2*u+1] = fma2(cb2, x1.y, o2[2*u+1]);
        }
    }

    ulonglong2* orow = (ulonglong2*)(out + ((size_t)i * Hc + h) * Dc);
#pragma unroll
    for (int u = 0; u < 16; u++) {
        ulonglong2 w2; w2.x = o2[2*u]; w2.y = o2[2*u+1];
        orow[u] = w2;
    }
}

// ---------------- launch ----------------
extern "C" void kernel_launch(void* const* d_in, const int* in_sizes, int n_in,
                              void* d_out, int out_size)
{
    (void)out_size;
    const float* qkv  = (const float*)d_in[0];
    const float* proj = (const float*)d_in[1];
    if (n_in >= 2 && in_sizes[0] < in_sizes[1]) {
        const float* tmp = qkv; qkv = proj; proj = tmp;
    }
    float* out = (float*)d_out;

    cudaFuncSetAttribute(k4_main, cudaFuncAttributeMaxDynamicSharedMemorySize,
                         SM4_FLOATS * (int)sizeof(float));

    dim3 grid(NC, Hc);
    k1_feat  <<<grid, 128>>>(qkv, proj);
    k2_kprime<<<grid, 128>>>(qkv);
    k4_main  <<<grid, 128, SM4_FLOATS * (int)sizeof(float)>>>(qkv, proj, out);
}

// round 6
// speedup vs baseline: 1.9538x; 1.0627x over previous
#include <cuda_runtime.h>
#include <math.h>

// Problem constants (B=1)
#define Lc     2048
#define Hc     16
#define Dc     64
#define Mc     24
#define Wc     128
#define CHUNK  128
#define NC     16
#define SCALEc 0.125f
#define EPSc   1e-4f
#define DN     0.35355339059327373f   // sqrt(0.125)
#define LN24   3.1780538303479458f    // log(24)

typedef unsigned long long U64;

__device__ __forceinline__ U64 fma2(U64 a, U64 b, U64 c) {
    U64 d; asm("fma.rn.f32x2 %0, %1, %2, %3;" : "=l"(d) : "l"(a), "l"(b), "l"(c)); return d;
}
__device__ __forceinline__ U64 mul2(U64 a, U64 b) {
    U64 d; asm("mul.rn.f32x2 %0, %1, %2;" : "=l"(d) : "l"(a), "l"(b)); return d;
}
__device__ __forceinline__ U64 add2(U64 a, U64 b) {
    U64 d; asm("add.rn.f32x2 %0, %1, %2;" : "=l"(d) : "l"(a), "l"(b)); return d;
}
__device__ __forceinline__ U64 pack2(float x, float y) {
    U64 d; asm("mov.b64 %0, {%1,%2};" : "=l"(d)
               : "r"(__float_as_uint(x)), "r"(__float_as_uint(y))); return d;
}
__device__ __forceinline__ float hadd2(U64 a) {
    unsigned lo, hi; asm("mov.b64 {%0,%1}, %2;" : "=r"(lo), "=r"(hi) : "l"(a));
    return __uint_as_float(lo) + __uint_as_float(hi);
}
__device__ __forceinline__ void unpack2(float& x, float& y, U64 a) {
    unsigned lo, hi; asm("mov.b64 {%0,%1}, %2;" : "=r"(lo), "=r"(hi) : "l"(a));
    x = __uint_as_float(lo); y = __uint_as_float(hi);
}

#define CP_COMMIT() asm volatile("cp.async.commit_group;")
#define CP_WAIT(n)  asm volatile("cp.async.wait_group %0;" :: "n"(n))

// ---------------- scratch ----------------
__device__ float g_kprime[Hc * Lc * Mc];          // p = exp(xd - xn - locmax_c)
__device__ float g_chunkmax[Hc * NC];             // locmax per (h,c)
__device__ float g_psum [Hc * NC * Mc];           // per-chunk sum of p
__device__ float g_pvsum[Hc * NC * Mc * Dc];      // per-chunk sum of p (x) v
__device__ float g_vsum [Hc * NC * Dc];           // per-chunk sum of v

__device__ __forceinline__ float sdot64(const float* krow, const U64* q2) {
    const ulonglong2* kr = (const ulonglong2*)krow;
    U64 a0, a1, a2, a3;
    {
        ulonglong2 x = kr[0]; a0 = mul2(q2[0], x.x); a1 = mul2(q2[1], x.y);
        ulonglong2 y = kr[1]; a2 = mul2(q2[2], y.x); a3 = mul2(q2[3], y.y);
    }
#pragma unroll
    for (int u = 2; u < 16; u += 2) {
        ulonglong2 x = kr[u];     a0 = fma2(q2[2*u],   x.x, a0); a1 = fma2(q2[2*u+1], x.y, a1);
        ulonglong2 y = kr[u + 1]; a2 = fma2(q2[2*u+2], y.x, a2); a3 = fma2(q2[2*u+3], y.y, a3);
    }
    return hadd2(add2(add2(a0, a1), add2(a2, a3)));
}

// ---------------- kernel 12: fused key features + chunk sums ----------------
// smem (floats): proj 1536 @0 | vbuf 8192 @1536 | kp 3200 @9728 | red 128 @12928
#define SM12_FLOATS 13056

__global__ void __launch_bounds__(128) k12_prep(const float* __restrict__ qkv,
                                                const float* __restrict__ proj)
{
    extern __shared__ float sm[];
    float* proj_s = sm;
    float* vbuf   = sm + 1536;
    float* kp_s   = sm + 9728;    // stride 25
    float* red    = sm + 12928;

    const int c = blockIdx.x, h = blockIdx.y, t = threadIdx.x;
    const int hc = h * NC + c;
    const int tilebase = c * CHUNK;

    for (int f = t; f < 384; f += 128)
        ((float4*)proj_s)[f] = ((const float4*)proj)[f];
    for (int f = t; f < 2048; f += 128) {
        int r = f >> 4, dv = f & 15;
        ((float4*)vbuf)[f] =
            ((const float4*)(qkv + ((size_t)((tilebase + r) * 3 + 2) * Hc + h) * Dc))[dv];
    }
    __syncthreads();

    // key row into packed regs
    U64 k2r[32];
    {
        const ulonglong2* kr = (const ulonglong2*)(qkv + ((size_t)((tilebase + t) * 3 + 1) * Hc + h) * Dc);
#pragma unroll
        for (int u = 0; u < 16; u++) { ulonglong2 x = kr[u]; k2r[2*u] = x.x; k2r[2*u+1] = x.y; }
    }
    float xn;
    {
        U64 a0 = mul2(k2r[0], k2r[0]), a1 = mul2(k2r[1], k2r[1]);
        U64 a2 = mul2(k2r[2], k2r[2]), a3 = mul2(k2r[3], k2r[3]);
#pragma unroll
        for (int u = 4; u < 32; u += 4) {
            a0 = fma2(k2r[u],   k2r[u],   a0);
            a1 = fma2(k2r[u+1], k2r[u+1], a1);
            a2 = fma2(k2r[u+2], k2r[u+2], a2);
            a3 = fma2(k2r[u+3], k2r[u+3], a3);
        }
        xn = hadd2(add2(add2(a0, a1), add2(a2, a3))) * 0.0625f;
    }
    float xd[Mc];
    float mx = -3.4e38f;
#pragma unroll
    for (int m = 0; m < Mc; m++) {
        xd[m] = sdot64(proj_s + m * Dc, k2r) * DN;
        mx = fmaxf(mx, xd[m]);
    }
    red[t] = mx;
    __syncthreads();
    for (int s = 64; s > 0; s >>= 1) {
        if (t < s) red[t] = fmaxf(red[t], red[t + s]);
        __syncthreads();
    }
    const float locmax = red[0];
    if (t == 0) g_chunkmax[hc] = locmax;

    float p[Mc];
#pragma unroll
    for (int m = 0; m < Mc; m++) {
        p[m] = __expf(xd[m] - xn - locmax);
        kp_s[t * 25 + m] = p[m];
    }
    {
        float4* kpo = (float4*)(g_kprime + ((size_t)h * Lc + tilebase + t) * Mc);
#pragma unroll
        for (int e = 0; e < 6; e++)
            kpo[e] = make_float4(p[4*e], p[4*e+1], p[4*e+2], p[4*e+3]);
    }
    __syncthreads();

    // pvsum (24x64), psum (24), vsum (64)
    float4* pvo4 = (float4*)(g_pvsum + (size_t)hc * Mc * Dc);
    const float4* vb4 = (const float4*)vbuf;
#pragma unroll
    for (int grp = 0; grp < 3; grp++) {
        int o = t + 128 * grp;
        int m = o >> 4, d4 = o & 15;
        float4 a = make_float4(0.f, 0.f, 0.f, 0.f);
        for (int row = 0; row < CHUNK; row++) {
            float kp = kp_s[row * 25 + m];
            float4 v = vb4[row * 16 + d4];
            a.x = fmaf(kp, v.x, a.x);
            a.y = fmaf(kp, v.y, a.y);
            a.z = fmaf(kp, v.z, a.z);
            a.w = fmaf(kp, v.w, a.w);
        }
        pvo4[o] = a;
    }
    if (t < Mc) {
        float a = 0.f;
        for (int row = 0; row < CHUNK; row++) a += kp_s[row * 25 + t];
        g_psum[hc * Mc + t] = a;
    }
    if (t < 16) {
        float4 a = make_float4(0.f, 0.f, 0.f, 0.f);
        for (int row = 0; row < CHUNK; row++) {
            float4 v = vb4[row * 16 + t];
            a.x += v.x; a.y += v.y; a.z += v.z; a.w += v.w;
        }
        ((float4*)(g_vsum + (size_t)hc * Dc))[t] = a;
    }
}

// ---------------- kernel 4: fused attention ----------
// smem (floats): K 16384 @0 | kp 6144 @16384 | proj 1536 @22528
//   | kvb 1536 @24064 | kb 32 @25600 | sv 64 @25632 | ring 2048 @25696
#define OFF_K    0
#define OFF_KP   16384
#define OFF_PROJ 22528
#define OFF_KVB  24064
#define OFF_KB   25600
#define OFF_SV   25632
#define OFF_RING 25696
#define SM4_FLOATS 27744

__device__ __forceinline__ float gdot24(const float* kprow, const U64* qp2) {
    const ulonglong2* pr = (const ulonglong2*)kprow;
    ulonglong2 y0 = pr[0], y1 = pr[1], y2 = pr[2];
    U64 g0 = mul2(qp2[0], y0.x), g1 = mul2(qp2[1], y0.y);
    g0 = fma2(qp2[2], y1.x, g0);  g1 = fma2(qp2[3], y1.y, g1);
    g0 = fma2(qp2[4], y2.x, g0);  g1 = fma2(qp2[5], y2.y, g1);
    ulonglong2 y3 = pr[3], y4 = pr[4], y5 = pr[5];
    g0 = fma2(qp2[6],  y3.x, g0); g1 = fma2(qp2[7],  y3.y, g1);
    g0 = fma2(qp2[8],  y4.x, g0); g1 = fma2(qp2[9],  y4.y, g1);
    g0 = fma2(qp2[10], y5.x, g0); g1 = fma2(qp2[11], y5.y, g1);
    return hadd2(add2(g0, g1));
}

__device__ __forceinline__ void vacc64(U64 c2, const float* vrow, U64* o2) {
    const ulonglong2* vr = (const ulonglong2*)vrow;
#pragma unroll
    for (int u = 0; u < 16; u++) {
        ulonglong2 x = vr[u];
        o2[2*u]   = fma2(c2, x.x, o2[2*u]);
        o2[2*u+1] = fma2(c2, x.y, o2[2*u+1]);
    }
}

__device__ __forceinline__ void stage2v(const float* __restrict__ qkv, int h,
                                        unsigned ringw_u32, int slot,
                                        int ra, int rb, int lane)
{
    int row = (lane < 16) ? ra : rb;
    const float* src = qkv + ((size_t)(row * 3 + 2) * Hc + h) * Dc + (lane & 15) * 4;
    unsigned dst = ringw_u32 + (unsigned)(slot * 512 + ((lane >> 4) * 256) + (lane & 15) * 16);
    asm volatile("cp.async.cg.shared.global [%0], [%1], 16;" :: "r"(dst), "l"(src));
}

__global__ void __launch_bounds__(128, 2) k4_main(const float* __restrict__ qkv,
                                                  const float* __restrict__ proj,
                                                  float* __restrict__ out)
{
    extern __shared__ float sm[];
    float* K_s    = sm + OFF_K;
    float* kp_s   = sm + OFF_KP;
    float* proj_s = sm + OFF_PROJ;
    float* kvb_s  = sm + OFF_KVB;
    float* kb_s   = sm + OFF_KB;
    float* sv_s   = sm + OFF_SV;
    float* ring   = sm + OFF_RING;

    const int c = blockIdx.x, h = blockIdx.y, t = threadIdx.x;
    const int warp = t >> 5, lane = t & 31;
    const int cstart = c * CHUNK;
    const int i = cstart + t;
    const int tilebase = (c > 0) ? (c - 1) * CHUNK : 0;
    const int nkeys    = (c > 0) ? 256 : 128;
    const int cb = (c > 0) ? 128 : 0;

    // ---- stabilizer + alpha factors ----
    float alf[NC];
    float kstab;
    {
        float cm[NC];
        kstab = -3.4e38f;
#pragma unroll
        for (int cc = 0; cc < NC; cc++) {
            cm[cc] = __ldg(&g_chunkmax[h * NC + cc]);
            kstab = fmaxf(kstab, cm[cc]);
        }
#pragma unroll
        for (int cc = 0; cc < NC; cc++) alf[cc] = __expf(cm[cc] - kstab);
    }
    const float alphaP = (c > 0) ? alf[c - 1] : 0.f;
    const float alphaC = alf[c];

    // ---- cooperative tile load ----
    for (int f = t; f < nkeys * 16; f += 128) {
        int r = f >> 4, dv = f & 15;
        ((float4*)K_s)[r * 16 + dv] =
            ((const float4*)(qkv + ((size_t)((tilebase + r) * 3 + 1) * Hc + h) * Dc))[dv];
    }
    {
        const float4* kpsrc = (const float4*)(g_kprime + ((size_t)h * Lc + tilebase) * Mc);
        for (int f = t; f < nkeys * 6; f += 128) ((float4*)kp_s)[f] = kpsrc[f];
        for (int f = t; f < 384; f += 128) ((float4*)proj_s)[f] = ((const float4*)proj)[f];
    }
    // ---- prefix reconstruction: kvb (alpha-weighted), kb, sv ----
#pragma unroll
    for (int g = 0; g < 3; g++) {
        int f = t + 128 * g;
        float4 a = make_float4(0.f, 0.f, 0.f, 0.f);
        for (int cc = 0; cc < c; cc++) {
            float al = alf[cc];
            float4 x = __ldg((const float4*)g_pvsum + (size_t)(h * NC + cc) * 384 + f);
            a.x = fmaf(al, x.x, a.x); a.y = fmaf(al, x.y, a.y);
            a.z = fmaf(al, x.z, a.z); a.w = fmaf(al, x.w, a.w);
        }
        ((float4*)kvb_s)[f] = a;
    }
    if (t < Mc) {
        float a = (float)c * (CHUNK * EPSc);
        for (int cc = 0; cc < c; cc++)
            a = fmaf(alf[cc], __ldg(&g_psum[(h * NC + cc) * Mc + t]), a);
        kb_s[t] = a;
    }
    if (t < 16) {
        float4 a = make_float4(0.f, 0.f, 0.f, 0.f);
        for (int cc = 0; cc < c; cc++) {
            float4 x = __ldg((const float4*)(g_vsum + (size_t)(h * NC + cc) * Dc) + t);
            a.x += x.x; a.y += x.y; a.z += x.z; a.w += x.w;
        }
        ((float4*)sv_s)[t] = a;
    }
    __syncthreads();

    // ---- query features ----
    U64 q2[32];
    {
        const ulonglong2* qr = (const ulonglong2*)(qkv + ((size_t)(i * 3) * Hc + h) * Dc);
#pragma unroll
        for (int u = 0; u < 16; u++) { ulonglong2 x = qr[u]; q2[2*u] = x.x; q2[2*u+1] = x.y; }
    }
    float xn;
    {
        U64 a0 = mul2(q2[0], q2[0]), a1 = mul2(q2[1], q2[1]);
        U64 a2 = mul2(q2[2], q2[2]), a3 = mul2(q2[3], q2[3]);
#pragma unroll
        for (int u = 4; u < 32; u += 4) {
            a0 = fma2(q2[u],   q2[u],   a0);
            a1 = fma2(q2[u+1], q2[u+1], a1);
            a2 = fma2(q2[u+2], q2[u+2], a2);
            a3 = fma2(q2[u+3], q2[u+3], a3);
        }
        xn = hadd2(add2(add2(a0, a1), add2(a2, a3))) * 0.0625f;
    }
    float xd[Mc];
    float qstab = -3.4e38f;
#pragma unroll
    for (int m = 0; m < Mc; m++) {
        float p = sdot64(proj_s + m * Dc, q2);
        xd[m] = p * DN;
        qstab = fmaxf(qstab, xd[m]);
    }
    U64 qp2[12];
    float qpsum = 0.f;
#pragma unroll
    for (int e = 0; e < 12; e++) {
        float a = __expf(xd[2*e]   - qstab) + EPSc;
        float b = __expf(xd[2*e+1] - qstab) + EPSc;
        qp2[e] = pack2(a, b);
        qpsum += a + b;
    }
    const float epsqp = EPSc * qpsum;

    const float gs = qstab - xn + kstab - LN24;
    float kbdot = 0.f;
#pragma unroll
    for (int e = 0; e < 12; e++) {
        float a, b; unpack2(a, b, qp2[e]);
        kbdot = fmaf(a, kb_s[2*e],     kbdot);
        kbdot = fmaf(b, kb_s[2*e + 1], kbdot);
    }

    // ---- pass 1: Z, Asc; cache (exp(s), g_eff) per key ----
    float2 sg[160];
    int idx = 0;
    float Z = 0.f, AscP = 0.f, AscC = 0.f;
    const int j0 = 32 * warp;
    if (c > 0) {
#pragma unroll 1
        for (int jr = j0; jr < 128; jr++) {
            float s = sdot64(K_s + jr * Dc, q2) * SCALEc;
            float gp = gdot24(kp_s + jr * Mc, qp2);
            float geff = fmaf(alphaP, gp, epsqp);
            float es = (jr >= t) ? __expf(s) : 0.f;
            float gg = (jr >= t) ? geff : 0.f;
            Z += es; AscP += gg;
            sg[idx++] = make_float2(es, gg);
        }
    }
    {
        const int jend = j0 + 32;
#pragma unroll 1
        for (int jc = 0; jc < jend; jc++) {
            float s = sdot64(K_s + (cb + jc) * Dc, q2) * SCALEc;
            float gp = gdot24(kp_s + (cb + jc) * Mc, qp2);
            float geff = fmaf(alphaC, gp, epsqp);
            float es = (jc <= t) ? __expf(s) : 0.f;
            float gg = (jc <= t) ? geff : 0.f;
            Z += es; AscC += gg;
            sg[idx++] = make_float2(es, gg);
        }
    }

    // ---- normalization scalars ----
    const float Asc = 0.875f * AscC - 0.125f * AscP;
    const float lse = __logf(Z);
    const float gln = __logf(fmaxf(kbdot + Asc, 1e-24f)) + gs;
    float a_ = fmaxf(lse, gln), b_ = fminf(lse, gln);
    const float lnorm = a_ + log1pf(__expf(b_ - a_));
    const float gps  = __expf(gs - lnorm);
    const float invZ = 1.f / Z;
    const float gpsP = -0.125f * gps;
    const float gpsC =  0.875f * gps;

    // ---- pass 2: output accumulation with cp.async V ring + cached coefs ----
    U64 o2[32];
#pragma unroll
    for (int u = 0; u < 32; u++) o2[u] = 0ULL;

    const unsigned ringw_u32 =
        (unsigned)__cvta_generic_to_shared(ring + warp * 512);
    const float* ringw = ring + warp * 512;
    int idx2 = 0;

    if (c > 0) {
        const int nbat = (128 - j0) >> 1;
#pragma unroll
        for (int p = 0; p < 3; p++) {
            int ra = j0 + 2*p;     if (ra > 127) ra = 127;
            int rb = j0 + 2*p + 1; if (rb > 127) rb = 127;
            stage2v(qkv, h, ringw_u32, p & 3, tilebase + ra, tilebase + rb, lane);
            CP_COMMIT();
        }
#pragma unroll 1
        for (int b = 0; b < nbat; b++) {
            int sp = b + 3;
            int ra = j0 + 2*sp;     if (ra > 127) ra = 127;
            int rb = j0 + 2*sp + 1; if (rb > 127) rb = 127;
            stage2v(qkv, h, ringw_u32, sp & 3, tilebase + ra, tilebase + rb, lane);
            CP_COMMIT();
            CP_WAIT(3);
            __syncwarp();
            const float* vb = ringw + (b & 3) * 128;
#pragma unroll
            for (int e = 0; e < 2; e++) {
                float2 sgv = sg[idx2++];
                float coef = fmaf(invZ, sgv.x, gpsP * sgv.y);
                vacc64(pack2(coef, coef), vb + e * 64, o2);
            }
        }
        CP_WAIT(0);
        __syncwarp();
    }
    {
        const int jend = j0 + 32;
        const int nbat = jend >> 1;
#pragma unroll
        for (int p = 0; p < 3; p++) {
            int ra = 2*p;     if (ra > jend - 1) ra = jend - 1;
            int rb = 2*p + 1; if (rb > jend - 1) rb = jend - 1;
            stage2v(qkv, h, ringw_u32, p & 3, cstart + ra, cstart + rb, lane);
            CP_COMMIT();
        }
#pragma unroll 1
        for (int b = 0; b < nbat; b++) {
            int sp = b + 3;
            int ra = 2*sp;     if (ra > jend - 1) ra = jend - 1;
            int rb = 2*sp + 1; if (rb > jend - 1) rb = jend - 1;
            stage2v(qkv, h, ringw_u32, sp & 3, cstart + ra, cstart + rb, lane);
            CP_COMMIT();
            CP_WAIT(3);
            __syncwarp();
            const float* vb = ringw + (b & 3) * 128;
#pragma unroll
            for (int e = 0; e < 2; e++) {
                float2 sgv = sg[idx2++];
                float coef = fmaf(invZ, sgv.x, gpsC * sgv.y);
                vacc64(pack2(coef, coef), vb + e * 64, o2);
            }
        }
        CP_WAIT(0);
        __syncwarp();
    }

    // ---- epilogue: o += gps * (q' . KVbase_alpha) + gps*qpsum*EPS * sv ----
#pragma unroll
    for (int e = 0; e < 12; e++) {
        float qa, qb; unpack2(qa, qb, qp2[e]);
        U64 ca  = pack2(gps * qa, gps * qa);
        U64 cb2 = pack2(gps * qb, gps * qb);
        const ulonglong2* r0 = (const ulonglong2*)(kvb_s + (2*e) * Dc);
        const ulonglong2* r1 = (const ulonglong2*)(kvb_s + (2*e + 1) * Dc);
#pragma unroll
        for (int u = 0; u < 16; u++) {
            ulonglong2 x0 = r0[u];
            ulonglong2 x1 = r1[u];
            o2[2*u]   = fma2(ca,  x0.x, o2[2*u]);
            o2[2*u+1] = fma2(ca,  x0.y, o2[2*u+1]);
            o2[2*u]   = fma2(cb2, x1.x, o2[2*u]);
            o2[2*u+1] = fma2(cb2, x1.y, o2[2*u+1]);
        }
    }
    {
        float csv = gps * epsqp;
        U64 c2 = pack2(csv, csv);
        vacc64(c2, sv_s, o2);
    }

    ulonglong2* orow = (ulonglong2*)(out + ((size_t)i * Hc + h) * Dc);
#pragma unroll
    for (int u = 0; u < 16; u++) {
        ulonglong2 w2; w2.x = o2[2*u]; w2.y = o2[2*u+1];
        orow[u] = w2;
    }
}

// ---------------- launch ----------------
extern "C" void kernel_launch(void* const* d_in, const int* in_sizes, int n_in,
                              void* d_out, int out_size)
{
    (void)out_size;
    const float* qkv  = (const float*)d_in[0];
    const float* proj = (const float*)d_in[1];
    if (n_in >= 2 && in_sizes[0] < in_sizes[1]) {
        const float* tmp = qkv; qkv = proj; proj = tmp;
    }
    float* out = (float*)d_out;

    cudaFuncSetAttribute(k12_prep, cudaFuncAttributeMaxDynamicSharedMemorySize,
                         SM12_FLOATS * (int)sizeof(float));
    cudaFuncSetAttribute(k4_main, cudaFuncAttributeMaxDynamicSharedMemorySize,
                         SM4_FLOATS * (int)sizeof(float));

    dim3 grid(NC, Hc);
    k12_prep<<<grid, 128, SM12_FLOATS * (int)sizeof(float)>>>(qkv, proj);
    k4_main <<<grid, 128, SM4_FLOATS * (int)sizeof(float)>>>(qkv, proj, out);
}